// round 10
// baseline (speedup 1.0000x reference)
#include <cuda_runtime.h>
#include <cuda_fp16.h>
#include <cstdint>

// Problem constants
#define BB 16384
#define DD 1024
#define HH 2048
#define EE 4
#define CC 3
#define NN 8192   // E*H  (folded single GEMM N)
#define KK 1024   // D

// GEMM tiling (HMMA mma.sync path; tcgen05 is 'a'-gated and unavailable here)
#define BM 128
#define BN 128
#define BK 64
#define STAGES 3
#define APAD 8
#define BPAD 8
#define ASTR (BK + APAD)     // 72 halves
#define BSTR (BN + BPAD)     // 136 halves
#define NBLK (NN / BN)       // 64
#define MBLK (BB / BM)       // 128
#define KTILES (KK / BK)     // 16

// dynamic smem layout (bytes)
#define A_STAGE_B (BM * ASTR * 2)              // 18432
#define B_STAGE_B (BK * BSTR * 2)              // 17408
#define OFF_A 0
#define OFF_B (STAGES * A_STAGE_B)             // 55296
#define OFF_BIAS (OFF_B + STAGES * B_STAGE_B)  // 107520
#define OFF_W2 (OFF_BIAS + 512)                // 108032 (128 floats bias)
#define OFF_RED (OFF_W2 + 1536)                // 109568 (128*3 floats w2)
#define SMEM_TOTAL (OFF_RED + 3072)            // 112640 (red 2*3*128 floats)

// ---------------- scratch (static device globals; no allocs) ----------------
__device__ __align__(16) __half g_normed[(size_t)BB * DD];     // 32 MB  LN(x) fp16 [b][d]
__device__ __align__(16) __half g_w1h[(size_t)KK * NN];        // 16 MB  folded W1' [d][e*H+h]
__device__ __align__(16) float  g_bias1[NN];                   // folded b1 + lnb @ W1
__device__ __align__(16) float  g_gatew[(size_t)BB * EE];      // softmax gate weights
__device__ __align__(16) float  g_part[(size_t)NBLK * 3 * BB]; // 12 MB partials [nb][c][b]

__device__ __forceinline__ uint32_t smem_u32(const void* p) {
    return (uint32_t)__cvta_generic_to_shared(p);
}

// ---------------- kernel 1: rowwise LN + gate softmax ----------------
__global__ __launch_bounds__(256) void k_prep(const float* __restrict__ x,
                                              const float* __restrict__ gln_g,
                                              const float* __restrict__ gln_b,
                                              const float* __restrict__ gate_w,
                                              const float* __restrict__ gate_b) {
    __shared__ float s_red[8][2];
    __shared__ float s_gl[8][4];
    __shared__ float s_mr[2];

    const int row  = blockIdx.x;
    const int tid  = threadIdx.x;
    const int lane = tid & 31;
    const int wid  = tid >> 5;

    float4 v = ((const float4*)(x + (size_t)row * DD))[tid];
    float s = v.x + v.y + v.z + v.w;
    float q = v.x * v.x + v.y * v.y + v.z * v.z + v.w * v.w;
    #pragma unroll
    for (int o = 16; o; o >>= 1) {
        s += __shfl_xor_sync(0xffffffffu, s, o);
        q += __shfl_xor_sync(0xffffffffu, q, o);
    }
    if (lane == 0) { s_red[wid][0] = s; s_red[wid][1] = q; }
    __syncthreads();
    if (tid == 0) {
        float S = 0.f, Q = 0.f;
        #pragma unroll
        for (int i = 0; i < 8; i++) { S += s_red[i][0]; Q += s_red[i][1]; }
        float mu  = S * (1.0f / DD);
        float var = Q * (1.0f / DD) - mu * mu;
        s_mr[0] = mu;
        s_mr[1] = rsqrtf(var + 1e-5f);
    }
    __syncthreads();
    const float mu = s_mr[0], rstd = s_mr[1];

    float n0 = (v.x - mu) * rstd;
    float n1 = (v.y - mu) * rstd;
    float n2 = (v.z - mu) * rstd;
    float n3 = (v.w - mu) * rstd;

    __half2* hp = (__half2*)(g_normed + (size_t)row * DD);
    hp[tid * 2 + 0] = __floats2half2_rn(n0, n1);
    hp[tid * 2 + 1] = __floats2half2_rn(n2, n3);

    const int d = tid * 4;
    float nn[4] = {n0, n1, n2, n3};
    float gl0 = 0.f, gl1 = 0.f, gl2 = 0.f, gl3 = 0.f;
    #pragma unroll
    for (int j = 0; j < 4; j++) {
        float t = nn[j] * gln_g[d + j] + gln_b[d + j];
        const float4 wv = *(const float4*)(gate_w + (size_t)(d + j) * EE);
        gl0 += t * wv.x; gl1 += t * wv.y; gl2 += t * wv.z; gl3 += t * wv.w;
    }
    #pragma unroll
    for (int o = 16; o; o >>= 1) {
        gl0 += __shfl_xor_sync(0xffffffffu, gl0, o);
        gl1 += __shfl_xor_sync(0xffffffffu, gl1, o);
        gl2 += __shfl_xor_sync(0xffffffffu, gl2, o);
        gl3 += __shfl_xor_sync(0xffffffffu, gl3, o);
    }
    if (lane == 0) { s_gl[wid][0] = gl0; s_gl[wid][1] = gl1; s_gl[wid][2] = gl2; s_gl[wid][3] = gl3; }
    __syncthreads();
    if (tid == 0) {
        float l[4] = {gate_b[0], gate_b[1], gate_b[2], gate_b[3]};
        #pragma unroll
        for (int i = 0; i < 8; i++)
            #pragma unroll
            for (int e = 0; e < 4; e++) l[e] += s_gl[i][e];
        float m = fmaxf(fmaxf(l[0], l[1]), fmaxf(l[2], l[3]));
        float ex[4], Z = 0.f;
        #pragma unroll
        for (int e = 0; e < 4; e++) { ex[e] = __expf(l[e] - m); Z += ex[e]; }
        float iz = 1.0f / Z;
        #pragma unroll
        for (int e = 0; e < 4; e++) g_gatew[(size_t)row * 4 + e] = ex[e] * iz;
    }
}

// ---------------- kernel 2: init bias1 with b1 ----------------
__global__ __launch_bounds__(256) void k_bias_init(const float* __restrict__ b1) {
    const int i = blockIdx.x * 256 + threadIdx.x;
    g_bias1[i] = b1[i];
}

// ---------------- kernel 3: fold ln_g into W1 (fp16, [d][e*H+h]) + accumulate lnb@W1 into bias1 ----------------
__global__ __launch_bounds__(256) void k_convw1(const float* __restrict__ w1,
                                                const float* __restrict__ lng,
                                                const float* __restrict__ lnb) {
    const int tid = threadIdx.x;
    const int h   = blockIdx.x * 256 + tid;     // 0..2047
    const int d0  = blockIdx.y * 8;             // 0..1016 step 8
    const int e   = blockIdx.z;

    float acc = 0.f;
    #pragma unroll
    for (int i = 0; i < 8; i++) {
        const int d = d0 + i;
        const float w = w1[(size_t)(e * DD + d) * HH + h];
        const float g = lng[e * DD + d];
        g_w1h[(size_t)d * NN + e * HH + h] = __float2half_rn(w * g);
        acc += lnb[e * DD + d] * w;
    }
    atomicAdd(&g_bias1[e * HH + h], acc);
}

// ---------------- kernel 4: HMMA GEMM (BK=64, 3-stage cp.async) + GELU + W2 ----------------
__device__ __forceinline__ void load_tile(uint32_t sbase, int tid, int stage, int k0,
                                          const __half* __restrict__ gA,
                                          const __half* __restrict__ gB, int n0) {
    const uint32_t aBase = sbase + OFF_A + stage * A_STAGE_B;
    const uint32_t bBase = sbase + OFF_B + stage * B_STAGE_B;
    // A: 128 rows x 8 chunks(16B) = 1024 chunks
    #pragma unroll
    for (int i = 0; i < 8; i++) {
        const int c = tid + i * 128;
        const int ar = c >> 3, ac = (c & 7) * 8;
        const uint32_t dsta = aBase + (uint32_t)(ar * ASTR + ac) * 2;
        const void* srca = gA + (size_t)ar * KK + k0 + ac;
        asm volatile("cp.async.cg.shared.global [%0], [%1], 16;" :: "r"(dsta), "l"(srca));
    }
    // B: 64 rows x 16 chunks(16B) = 1024 chunks
    #pragma unroll
    for (int i = 0; i < 8; i++) {
        const int c = tid + i * 128;
        const int br = c >> 4, bc = (c & 15) * 8;
        const uint32_t dstb = bBase + (uint32_t)(br * BSTR + bc) * 2;
        const void* srcb = gB + (size_t)(k0 + br) * NN + n0 + bc;
        asm volatile("cp.async.cg.shared.global [%0], [%1], 16;" :: "r"(dstb), "l"(srcb));
    }
    asm volatile("cp.async.commit_group;");
}

__global__ __launch_bounds__(128, 2) void k_gemm(const float* __restrict__ w2) {
    extern __shared__ __align__(16) char smem[];
    const uint32_t sbase = smem_u32(smem);
    const int tid  = threadIdx.x;
    const int lane = tid & 31;
    const int wid  = tid >> 5;
    const int wm   = wid >> 1;          // 0..1
    const int wn   = wid & 1;           // 0..1
    const int m_w  = wm * 64;
    const int n_w  = wn * 64;
    const int g    = lane >> 2;
    const int t    = lane & 3;

    const int nb = blockIdx.x;          // 0..63
    const int mb = blockIdx.y;          // 0..127
    const int m0 = mb * BM;
    const int n0 = nb * BN;

    float* bias_s = (float*)(smem + OFF_BIAS);
    float* w2_s   = (float*)(smem + OFF_W2);    // [128][3]
    float* red    = (float*)(smem + OFF_RED);   // [2][3][128]

    {
        bias_s[tid] = g_bias1[n0 + tid];
        const float* w2p = w2 + (size_t)(n0 + tid) * 3;
        w2_s[tid * 3 + 0] = w2p[0];
        w2_s[tid * 3 + 1] = w2p[1];
        w2_s[tid * 3 + 2] = w2p[2];
    }

    const __half* gA = g_normed + (size_t)m0 * KK;
    const __half* gB = g_w1h;

    float acc[4][8][4];
    #pragma unroll
    for (int i = 0; i < 4; i++)
        #pragma unroll
        for (int j = 0; j < 8; j++)
            #pragma unroll
            for (int k = 0; k < 4; k++) acc[i][j][k] = 0.f;

    // prologue: fill 2 of 3 stages
    load_tile(sbase, tid, 0, 0, gA, gB, n0);
    load_tile(sbase, tid, 1, BK, gA, gB, n0);

    for (int kt = 0; kt < KTILES; ++kt) {
        if (kt < KTILES - 1) asm volatile("cp.async.wait_group 1;");
        else                 asm volatile("cp.async.wait_group 0;");
        __syncthreads();

        if (kt + 2 < KTILES) {
            const int stL = (kt + 2) % STAGES;
            load_tile(sbase, tid, stL, (kt + 2) * BK, gA, gB, n0);
        }

        const int st = kt % STAGES;
        const uint32_t aSt = sbase + OFF_A + st * A_STAGE_B;
        const uint32_t bSt = sbase + OFF_B + st * B_STAGE_B;

        #pragma unroll
        for (int ks = 0; ks < 4; ++ks) {
            const int kk = ks * 16;
            // A fragments via ldmatrix x4 (non-trans): 64 rows x 16 k
            uint32_t a[4][4];
            #pragma unroll
            for (int mf = 0; mf < 4; ++mf) {
                const int row = m_w + mf * 16 + (lane & 15);
                const int col = kk + (lane >> 4) * 8;
                const uint32_t addr = aSt + (uint32_t)(row * ASTR + col) * 2;
                asm volatile("ldmatrix.sync.aligned.m8n8.x4.shared.b16 {%0,%1,%2,%3}, [%4];"
                             : "=r"(a[mf][0]), "=r"(a[mf][1]), "=r"(a[mf][2]), "=r"(a[mf][3])
                             : "r"(addr));
            }
            // B fragments via ldmatrix x4 trans: 16 k x 64 n
            uint32_t b[8][2];
            #pragma unroll
            for (int nf2 = 0; nf2 < 4; ++nf2) {
                const int q    = lane >> 3;
                const int krow = kk + (q & 1) * 8 + (lane & 7);
                const int ncol = n_w + nf2 * 16 + (q >> 1) * 8;
                const uint32_t addr = bSt + (uint32_t)(krow * BSTR + ncol) * 2;
                uint32_t d0, d1, d2, d3;
                asm volatile("ldmatrix.sync.aligned.m8n8.x4.trans.shared.b16 {%0,%1,%2,%3}, [%4];"
                             : "=r"(d0), "=r"(d1), "=r"(d2), "=r"(d3) : "r"(addr));
                b[nf2 * 2 + 0][0] = d0; b[nf2 * 2 + 0][1] = d1;
                b[nf2 * 2 + 1][0] = d2; b[nf2 * 2 + 1][1] = d3;
            }
            #pragma unroll
            for (int mf = 0; mf < 4; ++mf)
                #pragma unroll
                for (int nf = 0; nf < 8; ++nf) {
                    asm volatile(
                        "mma.sync.aligned.m16n8k16.row.col.f32.f16.f16.f32 "
                        "{%0,%1,%2,%3},{%4,%5,%6,%7},{%8,%9},{%0,%1,%2,%3};"
                        : "+f"(acc[mf][nf][0]), "+f"(acc[mf][nf][1]),
                          "+f"(acc[mf][nf][2]), "+f"(acc[mf][nf][3])
                        : "r"(a[mf][0]), "r"(a[mf][1]), "r"(a[mf][2]), "r"(a[mf][3]),
                          "r"(b[nf][0]), "r"(b[nf][1]));
                }
        }
    }
    __syncthreads();

    // Epilogue: z -> +bias1 -> exact GELU -> contract W2 (C=3) -> reduce
    #pragma unroll
    for (int mf = 0; mf < 4; ++mf) {
        #pragma unroll
        for (int rr = 0; rr < 2; ++rr) {
            float p0 = 0.f, p1 = 0.f, p2 = 0.f;
            #pragma unroll
            for (int nf = 0; nf < 8; ++nf) {
                #pragma unroll
                for (int cc = 0; cc < 2; ++cc) {
                    const int nl = n_w + nf * 8 + 2 * t + cc;
                    const float z  = acc[mf][nf][rr * 2 + cc] + bias_s[nl];
                    const float gl = 0.5f * z * (1.0f + erff(z * 0.7071067811865475f));
                    p0 += gl * w2_s[nl * 3 + 0];
                    p1 += gl * w2_s[nl * 3 + 1];
                    p2 += gl * w2_s[nl * 3 + 2];
                }
            }
            p0 += __shfl_xor_sync(0xffffffffu, p0, 1);
            p0 += __shfl_xor_sync(0xffffffffu, p0, 2);
            p1 += __shfl_xor_sync(0xffffffffu, p1, 1);
            p1 += __shfl_xor_sync(0xffffffffu, p1, 2);
            p2 += __shfl_xor_sync(0xffffffffu, p2, 1);
            p2 += __shfl_xor_sync(0xffffffffu, p2, 2);
            if (t == 0) {
                const int rl = m_w + mf * 16 + rr * 8 + g;
                red[(wn * 3 + 0) * 128 + rl] = p0;
                red[(wn * 3 + 1) * 128 + rl] = p1;
                red[(wn * 3 + 2) * 128 + rl] = p2;
            }
        }
    }
    __syncthreads();
    if (tid < 128) {
        #pragma unroll
        for (int c = 0; c < 3; c++) {
            const float v = red[c * 128 + tid] + red[(3 + c) * 128 + tid];
            g_part[((size_t)(nb * 3 + c)) * BB + m0 + tid] = v;
        }
    }
}

// ---------------- kernel 5: deterministic reduction over n-blocks + gating + b2 ----------------
__global__ __launch_bounds__(256) void k_final(const float* __restrict__ b2,
                                               float* __restrict__ out) {
    const int b = blockIdx.x * 256 + threadIdx.x;
    float gwv[4];
    #pragma unroll
    for (int e = 0; e < 4; e++) gwv[e] = g_gatew[(size_t)b * 4 + e];

    float o0 = gwv[0] * b2[0] + gwv[1] * b2[3] + gwv[2] * b2[6] + gwv[3] * b2[9];
    float o1 = gwv[0] * b2[1] + gwv[1] * b2[4] + gwv[2] * b2[7] + gwv[3] * b2[10];
    float o2 = gwv[0] * b2[2] + gwv[1] * b2[5] + gwv[2] * b2[8] + gwv[3] * b2[11];

    for (int nbk = 0; nbk < NBLK; ++nbk) {
        const float w = gwv[nbk >> 4];   // BN=128 -> 16 n-blocks per expert
        o0 += w * g_part[((size_t)(nbk * 3 + 0)) * BB + b];
        o1 += w * g_part[((size_t)(nbk * 3 + 1)) * BB + b];
        o2 += w * g_part[((size_t)(nbk * 3 + 2)) * BB + b];
    }
    out[(size_t)b * 3 + 0] = o0;
    out[(size_t)b * 3 + 1] = o1;
    out[(size_t)b * 3 + 2] = o2;
}

// ---------------- launch ----------------
extern "C" void kernel_launch(void* const* d_in, const int* in_sizes, int n_in,
                              void* d_out, int out_size) {
    (void)in_sizes; (void)n_in; (void)out_size;
    const float* x     = (const float*)d_in[0];
    const float* gln_g = (const float*)d_in[1];
    const float* gln_b = (const float*)d_in[2];
    const float* gate_w= (const float*)d_in[3];
    const float* gate_b= (const float*)d_in[4];
    const float* lng   = (const float*)d_in[5];
    const float* lnb   = (const float*)d_in[6];
    const float* w1    = (const float*)d_in[7];
    const float* b1    = (const float*)d_in[8];
    const float* w2    = (const float*)d_in[9];
    const float* b2    = (const float*)d_in[10];
    float* out = (float*)d_out;

    cudaFuncSetAttribute(k_gemm, cudaFuncAttributeMaxDynamicSharedMemorySize, SMEM_TOTAL);

    k_prep<<<BB, 256>>>(x, gln_g, gln_b, gate_w, gate_b);
    k_bias_init<<<NN / 256, 256>>>(b1);
    k_convw1<<<dim3(HH / 256, DD / 8, EE), 256>>>(w1, lng, lnb);
    k_gemm<<<dim3(NBLK, MBLK), 128, SMEM_TOTAL>>>(w2);
    k_final<<<BB / 256, 256>>>(b2, out);
}

// round 12
// speedup vs baseline: 1.1117x; 1.1117x over previous
#include <cuda_runtime.h>
#include <cuda_fp16.h>
#include <cstdint>

// Problem constants
#define BB 16384
#define DD 1024
#define HH 2048
#define EE 4
#define CC 3
#define NN 8192   // E*H  (folded single GEMM N)
#define KK 1024   // D

// GEMM tiling (HMMA mma.sync path; tcgen05 is 'a'-gated and unavailable here)
#define BM 128
#define BN 128
#define BK 32
#define STAGES 4
#define APAD 8
#define BPAD 8
#define ASTR (BK + APAD)     // 40 halves
#define BSTR (BN + BPAD)     // 136 halves
#define NBLK (NN / BN)       // 64
#define MBLK (BB / BM)       // 128
#define KTILES (KK / BK)     // 32

// dynamic smem layout (bytes)
#define A_STAGE_B (BM * ASTR * 2)              // 10240
#define B_STAGE_B (BK * BSTR * 2)              // 8704
#define OFF_A 0
#define OFF_B (STAGES * A_STAGE_B)             // 40960
#define OFF_BIAS (OFF_B + STAGES * B_STAGE_B)  // 75776
#define OFF_W2 (OFF_BIAS + 512)                // 76288  (128 floats bias)
#define OFF_RED (OFF_W2 + 1536)                // 77824  (128*3 floats w2)
#define SMEM_TOTAL (OFF_RED + 3072)            // 80896  (red 2*3*128 floats)

// ---------------- scratch (static device globals; no allocs) ----------------
__device__ __align__(16) __half g_normed[(size_t)BB * DD];     // 32 MB  LN(x) fp16 [b][d]
__device__ __align__(16) __half g_w1h[(size_t)KK * NN];        // 16 MB  folded W1' [d][e*H+h]
__device__ __align__(16) float  g_bias1[NN];                   // folded b1 + lnb @ W1
__device__ __align__(16) float  g_gatew[(size_t)BB * EE];      // softmax gate weights
__device__ __align__(16) float  g_part[(size_t)NBLK * 3 * BB]; // 12 MB partials [nb][c][b]

__device__ __forceinline__ uint32_t smem_u32(const void* p) {
    return (uint32_t)__cvta_generic_to_shared(p);
}

// ---------------- kernel 1: rowwise LN + gate softmax ----------------
__global__ __launch_bounds__(256) void k_prep(const float* __restrict__ x,
                                              const float* __restrict__ gln_g,
                                              const float* __restrict__ gln_b,
                                              const float* __restrict__ gate_w,
                                              const float* __restrict__ gate_b) {
    __shared__ float s_red[8][2];
    __shared__ float s_gl[8][4];
    __shared__ float s_mr[2];

    const int row  = blockIdx.x;
    const int tid  = threadIdx.x;
    const int lane = tid & 31;
    const int wid  = tid >> 5;

    float4 v = ((const float4*)(x + (size_t)row * DD))[tid];
    float s = v.x + v.y + v.z + v.w;
    float q = v.x * v.x + v.y * v.y + v.z * v.z + v.w * v.w;
    #pragma unroll
    for (int o = 16; o; o >>= 1) {
        s += __shfl_xor_sync(0xffffffffu, s, o);
        q += __shfl_xor_sync(0xffffffffu, q, o);
    }
    if (lane == 0) { s_red[wid][0] = s; s_red[wid][1] = q; }
    __syncthreads();
    if (tid == 0) {
        float S = 0.f, Q = 0.f;
        #pragma unroll
        for (int i = 0; i < 8; i++) { S += s_red[i][0]; Q += s_red[i][1]; }
        float mu  = S * (1.0f / DD);
        float var = Q * (1.0f / DD) - mu * mu;
        s_mr[0] = mu;
        s_mr[1] = rsqrtf(var + 1e-5f);
    }
    __syncthreads();
    const float mu = s_mr[0], rstd = s_mr[1];

    float n0 = (v.x - mu) * rstd;
    float n1 = (v.y - mu) * rstd;
    float n2 = (v.z - mu) * rstd;
    float n3 = (v.w - mu) * rstd;

    __half2* hp = (__half2*)(g_normed + (size_t)row * DD);
    hp[tid * 2 + 0] = __floats2half2_rn(n0, n1);
    hp[tid * 2 + 1] = __floats2half2_rn(n2, n3);

    const int d = tid * 4;
    float nn[4] = {n0, n1, n2, n3};
    float gl0 = 0.f, gl1 = 0.f, gl2 = 0.f, gl3 = 0.f;
    #pragma unroll
    for (int j = 0; j < 4; j++) {
        float t = nn[j] * gln_g[d + j] + gln_b[d + j];
        const float4 wv = *(const float4*)(gate_w + (size_t)(d + j) * EE);
        gl0 += t * wv.x; gl1 += t * wv.y; gl2 += t * wv.z; gl3 += t * wv.w;
    }
    #pragma unroll
    for (int o = 16; o; o >>= 1) {
        gl0 += __shfl_xor_sync(0xffffffffu, gl0, o);
        gl1 += __shfl_xor_sync(0xffffffffu, gl1, o);
        gl2 += __shfl_xor_sync(0xffffffffu, gl2, o);
        gl3 += __shfl_xor_sync(0xffffffffu, gl3, o);
    }
    if (lane == 0) { s_gl[wid][0] = gl0; s_gl[wid][1] = gl1; s_gl[wid][2] = gl2; s_gl[wid][3] = gl3; }
    __syncthreads();
    if (tid == 0) {
        float l[4] = {gate_b[0], gate_b[1], gate_b[2], gate_b[3]};
        #pragma unroll
        for (int i = 0; i < 8; i++)
            #pragma unroll
            for (int e = 0; e < 4; e++) l[e] += s_gl[i][e];
        float m = fmaxf(fmaxf(l[0], l[1]), fmaxf(l[2], l[3]));
        float ex[4], Z = 0.f;
        #pragma unroll
        for (int e = 0; e < 4; e++) { ex[e] = __expf(l[e] - m); Z += ex[e]; }
        float iz = 1.0f / Z;
        #pragma unroll
        for (int e = 0; e < 4; e++) g_gatew[(size_t)row * 4 + e] = ex[e] * iz;
    }
}

// ---------------- kernel 2: init bias1 with b1 ----------------
__global__ __launch_bounds__(256) void k_bias_init(const float* __restrict__ b1) {
    const int i = blockIdx.x * 256 + threadIdx.x;
    g_bias1[i] = b1[i];
}

// ---------------- kernel 3: fold ln_g into W1 (fp16, [d][e*H+h]) + accumulate lnb@W1 into bias1 ----------------
__global__ __launch_bounds__(256) void k_convw1(const float* __restrict__ w1,
                                                const float* __restrict__ lng,
                                                const float* __restrict__ lnb) {
    const int tid = threadIdx.x;
    const int h   = blockIdx.x * 256 + tid;     // 0..2047
    const int d0  = blockIdx.y * 8;             // 0..1016 step 8
    const int e   = blockIdx.z;

    float acc = 0.f;
    #pragma unroll
    for (int i = 0; i < 8; i++) {
        const int d = d0 + i;
        const float w = w1[(size_t)(e * DD + d) * HH + h];
        const float g = lng[e * DD + d];
        g_w1h[(size_t)d * NN + e * HH + h] = __float2half_rn(w * g);
        acc += lnb[e * DD + d] * w;
    }
    atomicAdd(&g_bias1[e * HH + h], acc);
}

// ---------------- kernel 4: HMMA GEMM (4-stage cp.async, reordered mainloop) + GELU + W2 ----------------
__device__ __forceinline__ void load_tile(uint32_t sbase, int tid, int stage, int k0,
                                          const __half* __restrict__ gA,
                                          const __half* __restrict__ gB, int n0) {
    const uint32_t aBase = sbase + OFF_A + stage * A_STAGE_B;
    const uint32_t bBase = sbase + OFF_B + stage * B_STAGE_B;
    #pragma unroll
    for (int i = 0; i < 4; i++) {
        const int c = tid + i * 128;
        // A: 128 rows x 4 chunks(16B)
        const int ar = c >> 2, ac = (c & 3) * 8;
        const uint32_t dsta = aBase + (uint32_t)(ar * ASTR + ac) * 2;
        const void* srca = gA + (size_t)ar * KK + k0 + ac;
        asm volatile("cp.async.cg.shared.global [%0], [%1], 16;" :: "r"(dsta), "l"(srca));
        // B: 32 rows x 16 chunks(16B)
        const int br = c >> 4, bc = (c & 15) * 8;
        const uint32_t dstb = bBase + (uint32_t)(br * BSTR + bc) * 2;
        const void* srcb = gB + (size_t)(k0 + br) * NN + n0 + bc;
        asm volatile("cp.async.cg.shared.global [%0], [%1], 16;" :: "r"(dstb), "l"(srcb));
    }
    asm volatile("cp.async.commit_group;");
}

__device__ __forceinline__ void ldsm_A(uint32_t aSt, int kk, int m_w, int lane,
                                       uint32_t (*a)[4]) {
    #pragma unroll
    for (int mf = 0; mf < 4; ++mf) {
        const int row = m_w + mf * 16 + (lane & 15);
        const int col = kk + (lane >> 4) * 8;
        const uint32_t addr = aSt + (uint32_t)(row * ASTR + col) * 2;
        asm volatile("ldmatrix.sync.aligned.m8n8.x4.shared.b16 {%0,%1,%2,%3}, [%4];"
                     : "=r"(a[mf][0]), "=r"(a[mf][1]), "=r"(a[mf][2]), "=r"(a[mf][3])
                     : "r"(addr));
    }
}

__device__ __forceinline__ void ldsm_B(uint32_t bSt, int kk, int n_w, int lane,
                                       uint32_t (*b)[2]) {
    #pragma unroll
    for (int nf2 = 0; nf2 < 4; ++nf2) {
        const int q    = lane >> 3;
        const int krow = kk + (q & 1) * 8 + (lane & 7);
        const int ncol = n_w + nf2 * 16 + (q >> 1) * 8;
        const uint32_t addr = bSt + (uint32_t)(krow * BSTR + ncol) * 2;
        uint32_t d0, d1, d2, d3;
        asm volatile("ldmatrix.sync.aligned.m8n8.x4.trans.shared.b16 {%0,%1,%2,%3}, [%4];"
                     : "=r"(d0), "=r"(d1), "=r"(d2), "=r"(d3) : "r"(addr));
        b[nf2 * 2 + 0][0] = d0; b[nf2 * 2 + 0][1] = d1;
        b[nf2 * 2 + 1][0] = d2; b[nf2 * 2 + 1][1] = d3;
    }
}

__global__ __launch_bounds__(128, 2) void k_gemm(const float* __restrict__ w2) {
    extern __shared__ __align__(16) char smem[];
    const uint32_t sbase = smem_u32(smem);
    const int tid  = threadIdx.x;
    const int lane = tid & 31;
    const int wid  = tid >> 5;
    const int wm   = wid >> 1;          // 0..1
    const int wn   = wid & 1;           // 0..1
    const int m_w  = wm * 64;
    const int n_w  = wn * 64;
    const int g    = lane >> 2;
    const int t    = lane & 3;

    const int nb = blockIdx.x;          // 0..63
    const int mb = blockIdx.y;          // 0..127
    const int m0 = mb * BM;
    const int n0 = nb * BN;

    float* bias_s = (float*)(smem + OFF_BIAS);
    float* w2_s   = (float*)(smem + OFF_W2);    // [128][3]
    float* red    = (float*)(smem + OFF_RED);   // [2][3][128]

    {
        bias_s[tid] = g_bias1[n0 + tid];
        const float* w2p = w2 + (size_t)(n0 + tid) * 3;
        w2_s[tid * 3 + 0] = w2p[0];
        w2_s[tid * 3 + 1] = w2p[1];
        w2_s[tid * 3 + 2] = w2p[2];
    }

    const __half* gA = g_normed + (size_t)m0 * KK;
    const __half* gB = g_w1h;

    float acc[4][8][4];
    #pragma unroll
    for (int i = 0; i < 4; i++)
        #pragma unroll
        for (int j = 0; j < 8; j++)
            #pragma unroll
            for (int k = 0; k < 4; k++) acc[i][j][k] = 0.f;

    // prologue: fill 3 stages
    load_tile(sbase, tid, 0, 0, gA, gB, n0);
    load_tile(sbase, tid, 1, BK, gA, gB, n0);
    load_tile(sbase, tid, 2, 2 * BK, gA, gB, n0);

    for (int kt = 0; kt < KTILES; ++kt) {
        if (kt < KTILES - 2)       asm volatile("cp.async.wait_group 2;");
        else if (kt == KTILES - 2) asm volatile("cp.async.wait_group 1;");
        else                       asm volatile("cp.async.wait_group 0;");
        __syncthreads();

        const int st = kt & 3;
        const uint32_t aSt = sbase + OFF_A + st * A_STAGE_B;
        const uint32_t bSt = sbase + OFF_B + st * B_STAGE_B;

        uint32_t a[4][4];
        uint32_t b[8][2];

        // ks=0 fragment loads FIRST (source order is issue order: asm volatile)
        ldsm_A(aSt, 0, m_w, lane, a);
        ldsm_B(bSt, 0, n_w, lane, b);

        // gmem prefetch sits in the LDSM-latency shadow instead of the kt head
        if (kt + 3 < KTILES)
            load_tile(sbase, tid, (kt + 3) & 3, (kt + 3) * BK, gA, gB, n0);

        // ks=0 MMAs
        #pragma unroll
        for (int mf = 0; mf < 4; ++mf)
            #pragma unroll
            for (int nf = 0; nf < 8; ++nf) {
                asm volatile(
                    "mma.sync.aligned.m16n8k16.row.col.f32.f16.f16.f32 "
                    "{%0,%1,%2,%3},{%4,%5,%6,%7},{%8,%9},{%0,%1,%2,%3};"
                    : "+f"(acc[mf][nf][0]), "+f"(acc[mf][nf][1]),
                      "+f"(acc[mf][nf][2]), "+f"(acc[mf][nf][3])
                    : "r"(a[mf][0]), "r"(a[mf][1]), "r"(a[mf][2]), "r"(a[mf][3]),
                      "r"(b[nf][0]), "r"(b[nf][1]));
            }

        // ks=1 fragment loads, then MMAs (other warp's MMA stream covers this head)
        ldsm_A(aSt, 16, m_w, lane, a);
        ldsm_B(bSt, 16, n_w, lane, b);
        #pragma unroll
        for (int mf = 0; mf < 4; ++mf)
            #pragma unroll
            for (int nf = 0; nf < 8; ++nf) {
                asm volatile(
                    "mma.sync.aligned.m16n8k16.row.col.f32.f16.f16.f32 "
                    "{%0,%1,%2,%3},{%4,%5,%6,%7},{%8,%9},{%0,%1,%2,%3};"
                    : "+f"(acc[mf][nf][0]), "+f"(acc[mf][nf][1]),
                      "+f"(acc[mf][nf][2]), "+f"(acc[mf][nf][3])
                    : "r"(a[mf][0]), "r"(a[mf][1]), "r"(a[mf][2]), "r"(a[mf][3]),
                      "r"(b[nf][0]), "r"(b[nf][1]));
            }
    }
    __syncthreads();

    // Epilogue: z -> +bias1 -> exact GELU -> contract W2 (C=3) -> reduce
    #pragma unroll
    for (int mf = 0; mf < 4; ++mf) {
        #pragma unroll
        for (int rr = 0; rr < 2; ++rr) {
            float p0 = 0.f, p1 = 0.f, p2 = 0.f;
            #pragma unroll
            for (int nf = 0; nf < 8; ++nf) {
                #pragma unroll
                for (int cc = 0; cc < 2; ++cc) {
                    const int nl = n_w + nf * 8 + 2 * t + cc;
                    const float z  = acc[mf][nf][rr * 2 + cc] + bias_s[nl];
                    const float gl = 0.5f * z * (1.0f + erff(z * 0.7071067811865475f));
                    p0 += gl * w2_s[nl * 3 + 0];
                    p1 += gl * w2_s[nl * 3 + 1];
                    p2 += gl * w2_s[nl * 3 + 2];
                }
            }
            p0 += __shfl_xor_sync(0xffffffffu, p0, 1);
            p0 += __shfl_xor_sync(0xffffffffu, p0, 2);
            p1 += __shfl_xor_sync(0xffffffffu, p1, 1);
            p1 += __shfl_xor_sync(0xffffffffu, p1, 2);
            p2 += __shfl_xor_sync(0xffffffffu, p2, 1);
            p2 += __shfl_xor_sync(0xffffffffu, p2, 2);
            if (t == 0) {
                const int rl = m_w + mf * 16 + rr * 8 + g;
                red[(wn * 3 + 0) * 128 + rl] = p0;
                red[(wn * 3 + 1) * 128 + rl] = p1;
                red[(wn * 3 + 2) * 128 + rl] = p2;
            }
        }
    }
    __syncthreads();
    if (tid < 128) {
        #pragma unroll
        for (int c = 0; c < 3; c++) {
            const float v = red[c * 128 + tid] + red[(3 + c) * 128 + tid];
            g_part[((size_t)(nb * 3 + c)) * BB + m0 + tid] = v;
        }
    }
}

// ---------------- kernel 5: deterministic reduction over n-blocks + gating + b2 ----------------
__global__ __launch_bounds__(256) void k_final(const float* __restrict__ b2,
                                               float* __restrict__ out) {
    const int b = blockIdx.x * 256 + threadIdx.x;
    float gwv[4];
    #pragma unroll
    for (int e = 0; e < 4; e++) gwv[e] = g_gatew[(size_t)b * 4 + e];

    float o0 = gwv[0] * b2[0] + gwv[1] * b2[3] + gwv[2] * b2[6] + gwv[3] * b2[9];
    float o1 = gwv[0] * b2[1] + gwv[1] * b2[4] + gwv[2] * b2[7] + gwv[3] * b2[10];
    float o2 = gwv[0] * b2[2] + gwv[1] * b2[5] + gwv[2] * b2[8] + gwv[3] * b2[11];

    for (int nbk = 0; nbk < NBLK; ++nbk) {
        const float w = gwv[nbk >> 4];   // BN=128 -> 16 n-blocks per expert
        o0 += w * g_part[((size_t)(nbk * 3 + 0)) * BB + b];
        o1 += w * g_part[((size_t)(nbk * 3 + 1)) * BB + b];
        o2 += w * g_part[((size_t)(nbk * 3 + 2)) * BB + b];
    }
    out[(size_t)b * 3 + 0] = o0;
    out[(size_t)b * 3 + 1] = o1;
    out[(size_t)b * 3 + 2] = o2;
}

// ---------------- launch ----------------
extern "C" void kernel_launch(void* const* d_in, const int* in_sizes, int n_in,
                              void* d_out, int out_size) {
    (void)in_sizes; (void)n_in; (void)out_size;
    const float* x     = (const float*)d_in[0];
    const float* gln_g = (const float*)d_in[1];
    const float* gln_b = (const float*)d_in[2];
    const float* gate_w= (const float*)d_in[3];
    const float* gate_b= (const float*)d_in[4];
    const float* lng   = (const float*)d_in[5];
    const float* lnb   = (const float*)d_in[6];
    const float* w1    = (const float*)d_in[7];
    const float* b1    = (const float*)d_in[8];
    const float* w2    = (const float*)d_in[9];
    const float* b2    = (const float*)d_in[10];
    float* out = (float*)d_out;

    cudaFuncSetAttribute(k_gemm, cudaFuncAttributeMaxDynamicSharedMemorySize, SMEM_TOTAL);

    k_prep<<<BB, 256>>>(x, gln_g, gln_b, gate_w, gate_b);
    k_bias_init<<<NN / 256, 256>>>(b1);
    k_convw1<<<dim3(HH / 256, DD / 8, EE), 256>>>(w1, lng, lnb);
    k_gemm<<<dim3(NBLK, MBLK), 128, SMEM_TOTAL>>>(w2);
    k_final<<<BB / 256, 256>>>(b2, out);
}

// round 14
// speedup vs baseline: 1.2177x; 1.0953x over previous
#include <cuda_runtime.h>
#include <cuda.h>
#include <cuda_fp16.h>
#include <cstdint>

// Problem constants
#define BB 16384
#define DD 1024
#define HH 2048
#define EE 4
#define CC 3
#define NN 8192   // E*H  (folded single GEMM N)
#define KK 1024   // D

// GEMM tiling (HMMA mma.sync + TMA loads; tcgen05 is 'a'-gated and unavailable)
#define BM 128
#define BN 128
#define BK 64                 // 64 halves = 128 B rows (SW128)
#define STAGES 3
#define NBLK (NN / BN)        // 64
#define MBLK (BB / BM)        // 128
#define KTILES (KK / BK)      // 16

// dynamic smem layout (bytes); stage = A tile (16 KB) + 2 B subtiles (8 KB each)
#define STG_B 32768
#define OFF_BSUB 16384
#define OFF_MBAR (STAGES * STG_B)          // 98304 (3 mbarriers, 8 B each)
#define OFF_BIAS (OFF_MBAR + 64)           // 98368 (128 floats bias)
#define OFF_W2 (OFF_BIAS + 512)            // 98880 (128*3 floats w2)
#define OFF_RED (OFF_W2 + 1536)            // 100416 (2*3*128 floats red)
#define SMEM_TOTAL (OFF_RED + 3072)        // 103488

// ---------------- scratch (static device globals; no allocs) ----------------
__device__ __align__(256) __half g_normed[(size_t)BB * DD];     // 32 MB  LN(x) fp16 [b][d]
__device__ __align__(256) __half g_w1h[(size_t)KK * NN];        // 16 MB  folded W1' [d][e*H+h]
__device__ __align__(16) float  g_bias1[NN];                    // folded b1 + lnb @ W1
__device__ __align__(16) float  g_gatew[(size_t)BB * EE];       // softmax gate weights
__device__ __align__(16) float  g_part[(size_t)NBLK * 3 * BB];  // 12 MB partials [nb][c][b]

__device__ __forceinline__ uint32_t smem_u32(const void* p) {
    return (uint32_t)__cvta_generic_to_shared(p);
}

// ---------------- kernel 1: rowwise LN + gate softmax ----------------
__global__ __launch_bounds__(256) void k_prep(const float* __restrict__ x,
                                              const float* __restrict__ gln_g,
                                              const float* __restrict__ gln_b,
                                              const float* __restrict__ gate_w,
                                              const float* __restrict__ gate_b) {
    __shared__ float s_red[8][2];
    __shared__ float s_gl[8][4];
    __shared__ float s_mr[2];

    const int row  = blockIdx.x;
    const int tid  = threadIdx.x;
    const int lane = tid & 31;
    const int wid  = tid >> 5;

    float4 v = ((const float4*)(x + (size_t)row * DD))[tid];
    float s = v.x + v.y + v.z + v.w;
    float q = v.x * v.x + v.y * v.y + v.z * v.z + v.w * v.w;
    #pragma unroll
    for (int o = 16; o; o >>= 1) {
        s += __shfl_xor_sync(0xffffffffu, s, o);
        q += __shfl_xor_sync(0xffffffffu, q, o);
    }
    if (lane == 0) { s_red[wid][0] = s; s_red[wid][1] = q; }
    __syncthreads();
    if (tid == 0) {
        float S = 0.f, Q = 0.f;
        #pragma unroll
        for (int i = 0; i < 8; i++) { S += s_red[i][0]; Q += s_red[i][1]; }
        float mu  = S * (1.0f / DD);
        float var = Q * (1.0f / DD) - mu * mu;
        s_mr[0] = mu;
        s_mr[1] = rsqrtf(var + 1e-5f);
    }
    __syncthreads();
    const float mu = s_mr[0], rstd = s_mr[1];

    float n0 = (v.x - mu) * rstd;
    float n1 = (v.y - mu) * rstd;
    float n2 = (v.z - mu) * rstd;
    float n3 = (v.w - mu) * rstd;

    __half2* hp = (__half2*)(g_normed + (size_t)row * DD);
    hp[tid * 2 + 0] = __floats2half2_rn(n0, n1);
    hp[tid * 2 + 1] = __floats2half2_rn(n2, n3);

    const int d = tid * 4;
    float nn[4] = {n0, n1, n2, n3};
    float gl0 = 0.f, gl1 = 0.f, gl2 = 0.f, gl3 = 0.f;
    #pragma unroll
    for (int j = 0; j < 4; j++) {
        float t = nn[j] * gln_g[d + j] + gln_b[d + j];
        const float4 wv = *(const float4*)(gate_w + (size_t)(d + j) * EE);
        gl0 += t * wv.x; gl1 += t * wv.y; gl2 += t * wv.z; gl3 += t * wv.w;
    }
    #pragma unroll
    for (int o = 16; o; o >>= 1) {
        gl0 += __shfl_xor_sync(0xffffffffu, gl0, o);
        gl1 += __shfl_xor_sync(0xffffffffu, gl1, o);
        gl2 += __shfl_xor_sync(0xffffffffu, gl2, o);
        gl3 += __shfl_xor_sync(0xffffffffu, gl3, o);
    }
    if (lane == 0) { s_gl[wid][0] = gl0; s_gl[wid][1] = gl1; s_gl[wid][2] = gl2; s_gl[wid][3] = gl3; }
    __syncthreads();
    if (tid == 0) {
        float l[4] = {gate_b[0], gate_b[1], gate_b[2], gate_b[3]};
        #pragma unroll
        for (int i = 0; i < 8; i++)
            #pragma unroll
            for (int e = 0; e < 4; e++) l[e] += s_gl[i][e];
        float m = fmaxf(fmaxf(l[0], l[1]), fmaxf(l[2], l[3]));
        float ex[4], Z = 0.f;
        #pragma unroll
        for (int e = 0; e < 4; e++) { ex[e] = __expf(l[e] - m); Z += ex[e]; }
        float iz = 1.0f / Z;
        #pragma unroll
        for (int e = 0; e < 4; e++) g_gatew[(size_t)row * 4 + e] = ex[e] * iz;
    }
}

// ---------------- kernel 2: init bias1 with b1 ----------------
__global__ __launch_bounds__(256) void k_bias_init(const float* __restrict__ b1) {
    const int i = blockIdx.x * 256 + threadIdx.x;
    g_bias1[i] = b1[i];
}

// ---------------- kernel 3: fold ln_g into W1 (fp16, [d][e*H+h]) + accumulate lnb@W1 into bias1 ----------------
__global__ __launch_bounds__(256) void k_convw1(const float* __restrict__ w1,
                                                const float* __restrict__ lng,
                                                const float* __restrict__ lnb) {
    const int tid = threadIdx.x;
    const int h   = blockIdx.x * 256 + tid;     // 0..2047
    const int d0  = blockIdx.y * 8;             // 0..1016 step 8
    const int e   = blockIdx.z;

    float acc = 0.f;
    #pragma unroll
    for (int i = 0; i < 8; i++) {
        const int d = d0 + i;
        const float w = w1[(size_t)(e * DD + d) * HH + h];
        const float g = lng[e * DD + d];
        g_w1h[(size_t)d * NN + e * HH + h] = __float2half_rn(w * g);
        acc += lnb[e * DD + d] * w;
    }
    atomicAdd(&g_bias1[e * HH + h], acc);
}

// ---------------- kernel 4: HMMA GEMM with TMA loads + mbarrier pipeline ----------------
#define MBARRIER_WAIT_PARITY(addr, par) do {                                   \
    uint32_t _m = (addr); uint32_t _p = (par); uint32_t _done;                 \
    asm volatile("{\n\t.reg .pred p;\n\t"                                      \
        "mbarrier.try_wait.parity.acquire.cta.shared::cta.b64 p, [%1], %2;\n\t"\
        "selp.b32 %0, 1, 0, p;\n\t}" : "=r"(_done) : "r"(_m), "r"(_p) : "memory"); \
    if (!_done) {                                                              \
        asm volatile("{\n\t.reg .pred P1;\n\t"                                 \
            "W_%=:\n\t"                                                        \
            "mbarrier.try_wait.parity.acquire.cta.shared::cta.b64 P1, [%0], %1, 0x989680;\n\t" \
            "@P1 bra.uni D_%=;\n\t"                                            \
            "bra.uni W_%=;\n\t"                                                \
            "D_%=:\n\t}" :: "r"(_m), "r"(_p) : "memory");                      \
    }                                                                          \
} while (0)

__device__ __forceinline__ void tma_issue(uint32_t sbase, const CUtensorMap* tA,
                                          const CUtensorMap* tB, int kt, int m0, int n0) {
    const int st = kt % STAGES;
    const uint32_t stg = sbase + st * STG_B;
    const uint32_t mb  = sbase + OFF_MBAR + st * 8;
    asm volatile("mbarrier.arrive.expect_tx.shared.b64 _, [%0], %1;"
                 :: "r"(mb), "r"(32768u) : "memory");
    const int k0 = kt * BK;
    asm volatile("cp.async.bulk.tensor.2d.shared::cta.global.tile.mbarrier::complete_tx::bytes "
                 "[%0], [%1, {%2, %3}], [%4];"
                 :: "r"(stg), "l"(tA), "r"(k0), "r"(m0), "r"(mb) : "memory");
    asm volatile("cp.async.bulk.tensor.2d.shared::cta.global.tile.mbarrier::complete_tx::bytes "
                 "[%0], [%1, {%2, %3}], [%4];"
                 :: "r"(stg + OFF_BSUB), "l"(tB), "r"(n0), "r"(k0), "r"(mb) : "memory");
    asm volatile("cp.async.bulk.tensor.2d.shared::cta.global.tile.mbarrier::complete_tx::bytes "
                 "[%0], [%1, {%2, %3}], [%4];"
                 :: "r"(stg + OFF_BSUB + 8192), "l"(tB), "r"(n0 + 64), "r"(k0), "r"(mb) : "memory");
}

__device__ __forceinline__ uint32_t sw128(uint32_t off) {
    return off ^ ((off >> 3) & 0x70);
}

__device__ __forceinline__ void ldsm_A_sw(uint32_t aBase, int ks, int m_w, int lane,
                                          uint32_t (*a)[4]) {
    const int colb = ks * 32 + (lane >> 4) * 16;     // bytes within 128-B row
    #pragma unroll
    for (int mf = 0; mf < 4; ++mf) {
        const int row = m_w + mf * 16 + (lane & 15);
        const uint32_t off = (uint32_t)(row * 128 + colb);
        const uint32_t addr = aBase + sw128(off);
        asm volatile("ldmatrix.sync.aligned.m8n8.x4.shared.b16 {%0,%1,%2,%3}, [%4];"
                     : "=r"(a[mf][0]), "=r"(a[mf][1]), "=r"(a[mf][2]), "=r"(a[mf][3])
                     : "r"(addr));
    }
}

__device__ __forceinline__ void ldsm_B_sw(uint32_t bBase, int ks, int lane,
                                          uint32_t (*b)[2]) {
    const int q = lane >> 3;
    const int krow = ks * 16 + (q & 1) * 8 + (lane & 7);
    #pragma unroll
    for (int nf2 = 0; nf2 < 4; ++nf2) {
        const int colb = nf2 * 32 + (q >> 1) * 16;   // bytes within 128-B row (64 n-halves)
        const uint32_t off = (uint32_t)(krow * 128 + colb);
        const uint32_t addr = bBase + sw128(off);
        uint32_t d0, d1, d2, d3;
        asm volatile("ldmatrix.sync.aligned.m8n8.x4.trans.shared.b16 {%0,%1,%2,%3}, [%4];"
                     : "=r"(d0), "=r"(d1), "=r"(d2), "=r"(d3) : "r"(addr));
        b[nf2 * 2 + 0][0] = d0; b[nf2 * 2 + 0][1] = d1;
        b[nf2 * 2 + 1][0] = d2; b[nf2 * 2 + 1][1] = d3;
    }
}

__global__ __launch_bounds__(128, 2) void k_gemm(const __grid_constant__ CUtensorMap tmA,
                                                 const __grid_constant__ CUtensorMap tmB,
                                                 const float* __restrict__ w2) {
    extern __shared__ __align__(1024) char smem[];
    const uint32_t sbase = smem_u32(smem);
    const int tid  = threadIdx.x;
    const int lane = tid & 31;
    const int wid  = tid >> 5;
    const int wm   = wid >> 1;          // 0..1
    const int wn   = wid & 1;           // 0..1
    const int m_w  = wm * 64;
    const int g    = lane >> 2;
    const int t    = lane & 3;

    const int nb = blockIdx.x;          // 0..63
    const int mb = blockIdx.y;          // 0..127
    const int m0 = mb * BM;
    const int n0 = nb * BN;

    float* bias_s = (float*)(smem + OFF_BIAS);
    float* w2_s   = (float*)(smem + OFF_W2);    // [128][3]
    float* red    = (float*)(smem + OFF_RED);   // [2][3][128]

    if (tid == 0) {
        #pragma unroll
        for (int s = 0; s < STAGES; s++)
            asm volatile("mbarrier.init.shared.b64 [%0], 1;"
                         :: "r"(sbase + OFF_MBAR + s * 8) : "memory");
    }
    {
        bias_s[tid] = g_bias1[n0 + tid];
        const float* w2p = w2 + (size_t)(n0 + tid) * 3;
        w2_s[tid * 3 + 0] = w2p[0];
        w2_s[tid * 3 + 1] = w2p[1];
        w2_s[tid * 3 + 2] = w2p[2];
    }
    __syncthreads();

    if (tid == 0) {
        tma_issue(sbase, &tmA, &tmB, 0, m0, n0);
        tma_issue(sbase, &tmA, &tmB, 1, m0, n0);
    }

    float acc[4][8][4];
    #pragma unroll
    for (int i = 0; i < 4; i++)
        #pragma unroll
        for (int j = 0; j < 8; j++)
            #pragma unroll
            for (int k = 0; k < 4; k++) acc[i][j][k] = 0.f;

    for (int kt = 0; kt < KTILES; ++kt) {
        __syncthreads();    // all warps done reading stage (kt-1)%3; safe to overwrite
        if (tid == 0 && kt + 2 < KTILES)
            tma_issue(sbase, &tmA, &tmB, kt + 2, m0, n0);

        const int st = kt % STAGES;
        MBARRIER_WAIT_PARITY(sbase + OFF_MBAR + st * 8, (uint32_t)((kt / STAGES) & 1));

        const uint32_t aBase = sbase + st * STG_B;
        const uint32_t bBase = sbase + st * STG_B + OFF_BSUB + wn * 8192;

        #pragma unroll
        for (int ks = 0; ks < 4; ++ks) {
            uint32_t a[4][4];
            uint32_t b[8][2];
            ldsm_A_sw(aBase, ks, m_w, lane, a);
            ldsm_B_sw(bBase, ks, lane, b);
            #pragma unroll
            for (int mf = 0; mf < 4; ++mf)
                #pragma unroll
                for (int nf = 0; nf < 8; ++nf) {
                    asm volatile(
                        "mma.sync.aligned.m16n8k16.row.col.f32.f16.f16.f32 "
                        "{%0,%1,%2,%3},{%4,%5,%6,%7},{%8,%9},{%0,%1,%2,%3};"
                        : "+f"(acc[mf][nf][0]), "+f"(acc[mf][nf][1]),
                          "+f"(acc[mf][nf][2]), "+f"(acc[mf][nf][3])
                        : "r"(a[mf][0]), "r"(a[mf][1]), "r"(a[mf][2]), "r"(a[mf][3]),
                          "r"(b[nf][0]), "r"(b[nf][1]));
                }
        }
    }
    __syncthreads();

    // Epilogue: z -> +bias1 -> exact GELU -> contract W2 (C=3) -> reduce
    const int n_w = wn * 64;
    #pragma unroll
    for (int mf = 0; mf < 4; ++mf) {
        #pragma unroll
        for (int rr = 0; rr < 2; ++rr) {
            float p0 = 0.f, p1 = 0.f, p2 = 0.f;
            #pragma unroll
            for (int nf = 0; nf < 8; ++nf) {
                #pragma unroll
                for (int cc = 0; cc < 2; ++cc) {
                    const int nl = n_w + nf * 8 + 2 * t + cc;
                    const float z  = acc[mf][nf][rr * 2 + cc] + bias_s[nl];
                    const float gl = 0.5f * z * (1.0f + erff(z * 0.7071067811865475f));
                    p0 += gl * w2_s[nl * 3 + 0];
                    p1 += gl * w2_s[nl * 3 + 1];
                    p2 += gl * w2_s[nl * 3 + 2];
                }
            }
            p0 += __shfl_xor_sync(0xffffffffu, p0, 1);
            p0 += __shfl_xor_sync(0xffffffffu, p0, 2);
            p1 += __shfl_xor_sync(0xffffffffu, p1, 1);
            p1 += __shfl_xor_sync(0xffffffffu, p1, 2);
            p2 += __shfl_xor_sync(0xffffffffu, p2, 1);
            p2 += __shfl_xor_sync(0xffffffffu, p2, 2);
            if (t == 0) {
                const int rl = m_w + mf * 16 + rr * 8 + g;
                red[(wn * 3 + 0) * 128 + rl] = p0;
                red[(wn * 3 + 1) * 128 + rl] = p1;
                red[(wn * 3 + 2) * 128 + rl] = p2;
            }
        }
    }
    __syncthreads();
    if (tid < 128) {
        #pragma unroll
        for (int c = 0; c < 3; c++) {
            const float v = red[c * 128 + tid] + red[(3 + c) * 128 + tid];
            g_part[((size_t)(nb * 3 + c)) * BB + m0 + tid] = v;
        }
    }
}

// ---------------- kernel 5: deterministic reduction over n-blocks + gating + b2 ----------------
__global__ __launch_bounds__(256) void k_final(const float* __restrict__ b2,
                                               float* __restrict__ out) {
    const int b = blockIdx.x * 256 + threadIdx.x;
    float gwv[4];
    #pragma unroll
    for (int e = 0; e < 4; e++) gwv[e] = g_gatew[(size_t)b * 4 + e];

    float o0 = gwv[0] * b2[0] + gwv[1] * b2[3] + gwv[2] * b2[6] + gwv[3] * b2[9];
    float o1 = gwv[0] * b2[1] + gwv[1] * b2[4] + gwv[2] * b2[7] + gwv[3] * b2[10];
    float o2 = gwv[0] * b2[2] + gwv[1] * b2[5] + gwv[2] * b2[8] + gwv[3] * b2[11];

    for (int nbk = 0; nbk < NBLK; ++nbk) {
        const float w = gwv[nbk >> 4];   // BN=128 -> 16 n-blocks per expert
        o0 += w * g_part[((size_t)(nbk * 3 + 0)) * BB + b];
        o1 += w * g_part[((size_t)(nbk * 3 + 1)) * BB + b];
        o2 += w * g_part[((size_t)(nbk * 3 + 2)) * BB + b];
    }
    out[(size_t)b * 3 + 0] = o0;
    out[(size_t)b * 3 + 1] = o1;
    out[(size_t)b * 3 + 2] = o2;
}

// ---------------- launch ----------------
typedef CUresult (*EncodeFn)(CUtensorMap*, CUtensorMapDataType, cuuint32_t, void*,
                             const cuuint64_t*, const cuuint64_t*, const cuuint32_t*,
                             const cuuint32_t*, CUtensorMapInterleave, CUtensorMapSwizzle,
                             CUtensorMapL2promotion, CUtensorMapFloatOOBfill);

extern "C" void kernel_launch(void* const* d_in, const int* in_sizes, int n_in,
                              void* d_out, int out_size) {
    (void)in_sizes; (void)n_in; (void)out_size;
    const float* x     = (const float*)d_in[0];
    const float* gln_g = (const float*)d_in[1];
    const float* gln_b = (const float*)d_in[2];
    const float* gate_w= (const float*)d_in[3];
    const float* gate_b= (const float*)d_in[4];
    const float* lng   = (const float*)d_in[5];
    const float* lnb   = (const float*)d_in[6];
    const float* w1    = (const float*)d_in[7];
    const float* b1    = (const float*)d_in[8];
    const float* w2    = (const float*)d_in[9];
    const float* b2    = (const float*)d_in[10];
    float* out = (float*)d_out;

    // Build TMA descriptors (host-side, no allocation, deterministic, no -lcuda link)
    void* fn = nullptr;
    cudaDriverEntryPointQueryResult qr;
    cudaGetDriverEntryPointByVersion("cuTensorMapEncodeTiled", &fn, 12000,
                                     cudaEnableDefault, &qr);
    EncodeFn encode = (EncodeFn)fn;

    void* pA = nullptr; cudaGetSymbolAddress(&pA, g_normed);
    void* pB = nullptr; cudaGetSymbolAddress(&pB, g_w1h);

    CUtensorMap tmA{}, tmB{};
    {
        cuuint64_t dims[2]    = {(cuuint64_t)KK, (cuuint64_t)BB};
        cuuint64_t strides[1] = {(cuuint64_t)KK * 2};
        cuuint32_t box[2]     = {64, 128};
        cuuint32_t estr[2]    = {1, 1};
        encode(&tmA, CU_TENSOR_MAP_DATA_TYPE_FLOAT16, 2, pA, dims, strides, box, estr,
               CU_TENSOR_MAP_INTERLEAVE_NONE, CU_TENSOR_MAP_SWIZZLE_128B,
               CU_TENSOR_MAP_L2_PROMOTION_L2_128B, CU_TENSOR_MAP_FLOAT_OOB_FILL_NONE);
    }
    {
        cuuint64_t dims[2]    = {(cuuint64_t)NN, (cuuint64_t)KK};
        cuuint64_t strides[1] = {(cuuint64_t)NN * 2};
        cuuint32_t box[2]     = {64, 64};
        cuuint32_t estr[2]    = {1, 1};
        encode(&tmB, CU_TENSOR_MAP_DATA_TYPE_FLOAT16, 2, pB, dims, strides, box, estr,
               CU_TENSOR_MAP_INTERLEAVE_NONE, CU_TENSOR_MAP_SWIZZLE_128B,
               CU_TENSOR_MAP_L2_PROMOTION_L2_128B, CU_TENSOR_MAP_FLOAT_OOB_FILL_NONE);
    }

    cudaFuncSetAttribute(k_gemm, cudaFuncAttributeMaxDynamicSharedMemorySize, SMEM_TOTAL);

    k_prep<<<BB, 256>>>(x, gln_g, gln_b, gate_w, gate_b);
    k_bias_init<<<NN / 256, 256>>>(b1);
    k_convw1<<<dim3(HH / 256, DD / 8, EE), 256>>>(w1, lng, lnb);
    k_gemm<<<dim3(NBLK, MBLK), 128, SMEM_TOTAL>>>(tmA, tmB, w2);
    k_final<<<BB / 256, 256>>>(b2, out);
}